// round 11
// baseline (speedup 1.0000x reference)
#include <cuda_runtime.h>
#include <cuda_bf16.h>
#include <cstdint>
#include <math.h>

// Problem constants
#define BQ      4
#define CDIM    384
#define TC      1152          // 3*CDIM
#define HP      128
#define WP      128
#define HW      16384         // HP*WP
#define NHEAD   8
#define CH      48            // per-head channels
#define NSPLIT  32            // split-K for gram

// ---------------- scratch (device globals; no runtime allocation) -------------
__device__ float g_qkv[(long long)BQ * TC * HW];     // qkv after 1x1 conv
__device__ float g_dw [(long long)BQ * TC * HW];     // after depthwise 3x3
__device__ float g_normsq[BQ * 2 * CDIM];            // q,k channel squared L2 norms
__device__ float g_partial[(long long)BQ * NHEAD * CH * CH * NSPLIT];
__device__ float g_attn[BQ * NHEAD * CH * CH];
__device__ float g_P   [BQ * NHEAD * CH * CH];       // combined softmax mix
__device__ float g_W2  [BQ * CDIM * CDIM];           // proj @ blockdiag(P)

// bf16 split operands
__device__ __align__(16) __nv_bfloat16 g_Wh[TC * CDIM];
__device__ __align__(16) __nv_bfloat16 g_Wl[TC * CDIM];
__device__ __align__(16) __nv_bfloat16 g_Bh[(long long)BQ * HW * CDIM];  // X^T then V^T
__device__ __align__(16) __nv_bfloat16 g_Bl[(long long)BQ * HW * CDIM];
__device__ __align__(16) __nv_bfloat16 g_W2h[BQ * CDIM * CDIM];
__device__ __align__(16) __nv_bfloat16 g_W2l[BQ * CDIM * CDIM];

// ======================= HMMA (mma.sync) helpers ==============================
__device__ __forceinline__ uint32_t smem_u32(const void* p) {
    uint32_t a;
    asm("{ .reg .u64 t; cvta.to.shared.u64 t, %1; cvt.u32.u64 %0, t; }" : "=r"(a) : "l"(p));
    return a;
}
__device__ __forceinline__ void cp16(uint32_t s, const void* g) {
    asm volatile("cp.async.cg.shared.global [%0], [%1], 16;" :: "r"(s), "l"(g));
}
#define CP_COMMIT() asm volatile("cp.async.commit_group;" ::: "memory")
#define CP_WAIT(n)  asm volatile("cp.async.wait_group %0;" :: "n"(n) : "memory")

__device__ __forceinline__ void ldm4(uint32_t* r, uint32_t addr) {
    asm volatile("ldmatrix.sync.aligned.m8n8.x4.shared.b16 {%0,%1,%2,%3}, [%4];"
        : "=r"(r[0]), "=r"(r[1]), "=r"(r[2]), "=r"(r[3]) : "r"(addr));
}
__device__ __forceinline__ void mma16816(float* d, const uint32_t* a, uint32_t b0, uint32_t b1) {
    asm volatile("mma.sync.aligned.m16n8k16.row.col.f32.bf16.bf16.f32 "
        "{%0,%1,%2,%3}, {%4,%5,%6,%7}, {%8,%9}, {%0,%1,%2,%3};"
        : "+f"(d[0]), "+f"(d[1]), "+f"(d[2]), "+f"(d[3])
        : "r"(a[0]), "r"(a[1]), "r"(a[2]), "r"(a[3]), "r"(b0), "r"(b1));
}

#define SMEM_SWZ(x) ((x) ^ (((x) >> 3) & 0x70))
#define STAGE_BYTES 32768     // As 16KB + Bs 16KB
#define NC 18                 // 3 split-terms * 6 K-chunks of 64

// ======================= HMMA GEMM kernel =====================================
// C[M,16384] = A[M,384] * Bt[16384,384]^T  (3-way bf16 split accumulated in f32)
__global__ __launch_bounds__(256) void mma_gemm(
    const __nv_bfloat16* __restrict__ Ah, const __nv_bfloat16* __restrict__ Al,
    const __nv_bfloat16* __restrict__ Bh, const __nv_bfloat16* __restrict__ Bl,
    float* __restrict__ C, long long aB, long long bB, long long cB)
{
    extern __shared__ char smem[];
    const uint32_t sb = smem_u32(smem);
    const int tid = threadIdx.x, wid = tid >> 5, lid = tid & 31;
    const int b = blockIdx.z;
    Ah += b * aB; Al += b * aB; Bh += b * bB; Bl += b * bB; C += b * cB;
    const long long m0 = (long long)blockIdx.y * 128;
    const long long n0 = (long long)blockIdx.x * 128;

    const int warp_m = wid & 1, warp_n = wid >> 1;   // 2 x 4 warp grid
    const int rbaseA = warp_m * 64;                  // 64 M-rows per warp
    const int nbaseB = warp_n * 32;                  // 32 N-cols per warp
    const int lr = lid & 15, lh = lid >> 4;

    float acc[4][4][4];
#pragma unroll
    for (int mi = 0; mi < 4; mi++)
#pragma unroll
        for (int ni = 0; ni < 4; ni++)
#pragma unroll
            for (int q = 0; q < 4; q++) acc[mi][ni][q] = 0.f;

    // chunk c: term = c/6 (0: Ah*Bh, 1: Ah*Bl, 2: Al*Bh), K-offset = (c%6)*64
    auto load_chunk = [&](int c, int st) {
        const int term = c / 6, ko = (c % 6) * 64;
        const __nv_bfloat16* Ap = ((term == 2) ? Al : Ah) + m0 * CDIM + ko;
        const __nv_bfloat16* Bp = ((term == 1) ? Bl : Bh) + n0 * CDIM + ko;
        const uint32_t dA = sb + st * STAGE_BYTES;
        const uint32_t dB = dA + 16384;
#pragma unroll
        for (int i = 0; i < 4; i++) {
            const int lin = tid + i * 256;
            const int row = lin >> 3, seg = lin & 7;
            const uint32_t sw = SMEM_SWZ(row * 128 + seg * 16);
            const long long go = (long long)row * CDIM + seg * 8;
            cp16(dA + sw, Ap + go);
            cp16(dB + sw, Bp + go);
        }
    };

    load_chunk(0, 0); CP_COMMIT();

    for (int c = 0; c < NC; c++) {
        __syncthreads();                         // previous compute done everywhere
        if (c + 1 < NC) { load_chunk(c + 1, (c + 1) & 1); CP_COMMIT(); CP_WAIT(1); }
        else           { CP_WAIT(0); }
        __syncthreads();                         // stage (c&1) visible to all warps

        const uint32_t baseA = sb + (c & 1) * STAGE_BYTES;
        const uint32_t baseB = baseA + 16384;
#pragma unroll
        for (int ks = 0; ks < 4; ks++) {
            const int cb = ks * 32 + lh * 16;    // k-step byte offset (+8-col half per lane)
            uint32_t a[4][4], bf[2][4];
#pragma unroll
            for (int mi = 0; mi < 4; mi++) {
                const int row = rbaseA + mi * 16 + lr;
                ldm4(a[mi], baseA + SMEM_SWZ(row * 128 + cb));
            }
#pragma unroll
            for (int nh = 0; nh < 2; nh++) {
                const int row = nbaseB + nh * 16 + lr;
                ldm4(bf[nh], baseB + SMEM_SWZ(row * 128 + cb));
            }
#pragma unroll
            for (int mi = 0; mi < 4; mi++)
#pragma unroll
                for (int ni = 0; ni < 4; ni++)
                    mma16816(acc[mi][ni], a[mi],
                             bf[ni >> 1][ni & 1], bf[ni >> 1][2 + (ni & 1)]);
        }
    }

    // epilogue: direct stores (fragment mapping: c0,c1 @ (g,2t), c2,c3 @ (g+8,2t))
    const int g = lid >> 2, t2 = (lid & 3) * 2;
#pragma unroll
    for (int mi = 0; mi < 4; mi++)
#pragma unroll
        for (int ni = 0; ni < 4; ni++) {
            const long long row = m0 + rbaseA + mi * 16 + g;
            const long long col = n0 + nbaseB + ni * 8 + t2;
            float* cp = C + row * HW + col;
            *(float2*)cp              = make_float2(acc[mi][ni][0], acc[mi][ni][1]);
            *(float2*)(cp + 8LL * HW) = make_float2(acc[mi][ni][2], acc[mi][ni][3]);
        }
}

// ---------------- fp32 -> bf16 hi/lo elementwise ------------------------------
__global__ __launch_bounds__(256) void split_elems(
    const float* __restrict__ src, __nv_bfloat16* __restrict__ dh,
    __nv_bfloat16* __restrict__ dl, int n)
{
    int i = blockIdx.x * 256 + threadIdx.x;
    if (i < n) {
        float v = src[i];
        __nv_bfloat16 h = __float2bfloat16(v);
        dh[i] = h;
        dl[i] = __float2bfloat16(v - __bfloat162float(h));
    }
}

// ---------------- transpose [C][N] -> [N][C] + bf16 hi/lo split ---------------
__global__ __launch_bounds__(256) void transpose_split(
    const float* __restrict__ src, __nv_bfloat16* __restrict__ dh,
    __nv_bfloat16* __restrict__ dl, long long sBatch, long long dBatch)
{
    __shared__ float t[32][33];
    const int b = blockIdx.z;
    src += b * sBatch; dh += b * dBatch; dl += b * dBatch;
    const int n0 = blockIdx.x * 32, c0 = blockIdx.y * 32;
    const int tx = threadIdx.x, ty = threadIdx.y;   // 32 x 8
#pragma unroll
    for (int i = 0; i < 4; i++)
        t[ty + 8 * i][tx] = src[(long long)(c0 + ty + 8 * i) * HW + n0 + tx];
    __syncthreads();
#pragma unroll
    for (int i = 0; i < 4; i++) {
        float v = t[tx][ty + 8 * i];
        __nv_bfloat16 h = __float2bfloat16(v);
        long long o = (long long)(n0 + ty + 8 * i) * CDIM + c0 + tx;
        dh[o] = h;
        dl[o] = __float2bfloat16(v - __bfloat162float(h));
    }
}

// ---------------- zero the squared-norm accumulators --------------------------
__global__ void zero_normsq()
{
    int i = blockIdx.x * 256 + threadIdx.x;
    if (i < BQ * 2 * CDIM) g_normsq[i] = 0.f;
}

// ---------------- tiled depthwise 3x3 + fused q/k norm accumulation -----------
// block: 256 threads computes one 16x128 output strip of one (b, ch)
__global__ __launch_bounds__(256) void dwconv_kernel(const float* __restrict__ dw_w)
{
    const int strip = blockIdx.x;          // 0..7
    const int ch    = blockIdx.y;          // 0..1151
    const int b     = blockIdx.z;
    const int y0    = strip * 16;
    const float* in = g_qkv + ((long long)b * TC + ch) * HW;
    float* out      = g_dw  + ((long long)b * TC + ch) * HW;

    __shared__ float tile[18][132];
    const int tid = threadIdx.x;

    float w[9];
#pragma unroll
    for (int i = 0; i < 9; i++) w[i] = __ldg(dw_w + ch * 9 + i);

    // load 18 x 130 halo tile (x in [-1,128], y in [y0-1, y0+16])
    for (int i = tid; i < 18 * 130; i += 256) {
        const int r = i / 130, c = i % 130;
        const int yy = y0 + r - 1, xx = c - 1;
        float v = 0.f;
        if (yy >= 0 && yy < HP && xx >= 0 && xx < WP) v = in[yy * WP + xx];
        tile[r][c] = v;
    }
    __syncthreads();

    float ss = 0.f;
#pragma unroll
    for (int i = 0; i < 8; i++) {
        const int o = tid + i * 256;           // 0..2047
        const int r = o >> 7, c = o & 127;     // r 0..15, c 0..127
        float s = w[0] * tile[r][c]     + w[1] * tile[r][c + 1]     + w[2] * tile[r][c + 2]
                + w[3] * tile[r + 1][c] + w[4] * tile[r + 1][c + 1] + w[5] * tile[r + 1][c + 2]
                + w[6] * tile[r + 2][c] + w[7] * tile[r + 2][c + 1] + w[8] * tile[r + 2][c + 2];
        out[(y0 + r) * WP + c] = s;
        ss += s * s;
    }

    // fused squared-norm accumulation for q/k channels
    if (ch < 2 * CDIM) {
        __shared__ float red[8];
#pragma unroll
        for (int o = 16; o > 0; o >>= 1) ss += __shfl_xor_sync(0xFFFFFFFFu, ss, o);
        const int wd = tid >> 5, lane = tid & 31;
        if (lane == 0) red[wd] = ss;
        __syncthreads();
        if (wd == 0) {
            ss = (lane < 8) ? red[lane] : 0.f;
#pragma unroll
            for (int o = 4; o > 0; o >>= 1) ss += __shfl_xor_sync(0xFFFFFFFFu, ss, o);
            if (lane == 0) atomicAdd(&g_normsq[b * 2 * CDIM + ch], ss);
        }
    }
}

// ---------------- gram partials (split-K) -------------------------------------
__global__ __launch_bounds__(256) void gram_kernel()
{
    const int s = blockIdx.x;
    const int h = blockIdx.y;
    const int b = blockIdx.z;

    const float* qbase = g_dw + ((long long)b * TC + h * CH) * HW;
    const float* kbase = g_dw + ((long long)b * TC + CDIM + h * CH) * HW;

    __shared__ float qs[64][49];
    __shared__ float ks[64][49];

    const int tid = threadIdx.x;
    const int ty = tid >> 4, tx = tid & 15;
    const int i0 = ty * 3, j0 = tx * 3;

    float acc[3][3] = {{0.f,0.f,0.f},{0.f,0.f,0.f},{0.f,0.f,0.f}};

    const int nbase0 = s * (HW / NSPLIT);
    for (int nb = 0; nb < HW / NSPLIT; nb += 64) {
        const int nbase = nbase0 + nb;
#pragma unroll
        for (int t = 0; t < 3; t++) {
            int lin = tid + t * 256;
            int row = lin >> 4;
            int c4  = (lin & 15) * 4;
            float4 v = *(const float4*)(qbase + (long long)row * HW + nbase + c4);
            qs[c4 + 0][row] = v.x; qs[c4 + 1][row] = v.y;
            qs[c4 + 2][row] = v.z; qs[c4 + 3][row] = v.w;
            float4 u = *(const float4*)(kbase + (long long)row * HW + nbase + c4);
            ks[c4 + 0][row] = u.x; ks[c4 + 1][row] = u.y;
            ks[c4 + 2][row] = u.z; ks[c4 + 3][row] = u.w;
        }
        __syncthreads();
#pragma unroll 8
        for (int n = 0; n < 64; n++) {
            float q0 = qs[n][i0], q1 = qs[n][i0 + 1], q2 = qs[n][i0 + 2];
            float k0 = ks[n][j0], k1 = ks[n][j0 + 1], k2 = ks[n][j0 + 2];
            acc[0][0] += q0 * k0; acc[0][1] += q0 * k1; acc[0][2] += q0 * k2;
            acc[1][0] += q1 * k0; acc[1][1] += q1 * k1; acc[1][2] += q1 * k2;
            acc[2][0] += q2 * k0; acc[2][1] += q2 * k1; acc[2][2] += q2 * k2;
        }
        __syncthreads();
    }

    const int bh = b * NHEAD + h;
#pragma unroll
    for (int i = 0; i < 3; i++)
#pragma unroll
        for (int j = 0; j < 3; j++)
            g_partial[((long long)bh * CH * CH + (i0 + i) * CH + (j0 + j)) * NSPLIT + s] = acc[i][j];
}

// ---------------- reduce splits + scale by temperature / rsqrt(normsq) --------
__global__ __launch_bounds__(256) void attn_finalize_kernel(const float* __restrict__ temperature)
{
    const int bh = blockIdx.x;
    const int b = bh / NHEAD, h = bh % NHEAD;
    const float temp = temperature[h];
    for (int idx = threadIdx.x; idx < CH * CH; idx += 256) {
        int i = idx / CH, j = idx % CH;
        float sum = 0.f;
        const float* p = g_partial + ((long long)bh * CH * CH + idx) * NSPLIT;
#pragma unroll
        for (int s = 0; s < NSPLIT; s++) sum += p[s];
        float nq2 = g_normsq[b * 2 * CDIM + h * CH + i];
        float nk2 = g_normsq[b * 2 * CDIM + CDIM + h * CH + j];
        g_attn[bh * CH * CH + idx] = sum * temp * rsqrtf(nq2 * nk2);
    }
}

// ---------------- top-k softmax combine ---------------------------------------
__global__ void topk_kernel(const float* __restrict__ a1, const float* __restrict__ a2,
                            const float* __restrict__ a3, const float* __restrict__ a4)
{
    const int bh = blockIdx.x;
    const int i = threadIdx.x;
    if (i >= CH) return;

    const float* row = g_attn + bh * CH * CH + i * CH;
    float v[CH], srt[CH];
#pragma unroll
    for (int j = 0; j < CH; j++) { v[j] = row[j]; srt[j] = v[j]; }

    for (int a = 1; a < CH; a++) {
        float key = srt[a];
        int bb = a - 1;
        while (bb >= 0 && srt[bb] < key) { srt[bb + 1] = srt[bb]; bb--; }
        srt[bb + 1] = key;
    }

    const float m = srt[0];
    float e[CH];
#pragma unroll
    for (int j = 0; j < CH; j++) e[j] = expf(v[j] - m);

    const int kidx[4] = {23, 31, 35, 37};
    const float aw[4] = {a1[0], a2[0], a3[0], a4[0]};

    float P[CH];
#pragma unroll
    for (int j = 0; j < CH; j++) P[j] = 0.f;

    for (int l = 0; l < 4; l++) {
        float thr = srt[kidx[l]];
        float denom = 0.f;
        for (int j = 0; j < CH; j++) if (v[j] >= thr) denom += e[j];
        float sc = aw[l] / denom;
        for (int j = 0; j < CH; j++) if (v[j] >= thr) P[j] += sc * e[j];
    }

    float* out = g_P + bh * CH * CH + i * CH;
#pragma unroll
    for (int j = 0; j < CH; j++) out[j] = P[j];
}

// ---------------- W2[b] = proj @ blockdiag(P[b,h]) ----------------------------
__global__ __launch_bounds__(384) void w2_kernel(const float* __restrict__ proj)
{
    const int h = blockIdx.x, b = blockIdx.y;
    const int bh = b * NHEAD + h;
    const int o = threadIdx.x;

    __shared__ float Ps[CH][CH];
    for (int idx = o; idx < CH * CH; idx += 384)
        Ps[idx / CH][idx % CH] = g_P[bh * CH * CH + idx];
    __syncthreads();

    float pr[CH];
#pragma unroll
    for (int cl = 0; cl < CH; cl++) pr[cl] = proj[o * CDIM + h * CH + cl];

    float* wout = g_W2 + ((long long)b * CDIM + o) * CDIM + h * CH;
    for (int d = 0; d < CH; d++) {
        float s = 0.f;
#pragma unroll
        for (int cl = 0; cl < CH; cl++) s += pr[cl] * Ps[cl][d];
        wout[d] = s;
    }
}

// ---------------- launch ------------------------------------------------------
extern "C" void kernel_launch(void* const* d_in, const int* in_sizes, int n_in,
                              void* d_out, int out_size)
{
    const float* x      = (const float*)d_in[0];
    const float* qkv_w  = (const float*)d_in[1];
    const float* dw_w   = (const float*)d_in[2];
    const float* proj_w = (const float*)d_in[3];
    const float* temp   = (const float*)d_in[4];
    const float* a1     = (const float*)d_in[5];
    const float* a2     = (const float*)d_in[6];
    const float* a3     = (const float*)d_in[7];
    const float* a4     = (const float*)d_in[8];
    float* y            = (float*)d_out;

    void* p;
    cudaGetSymbolAddress(&p, g_qkv); float* qkvp = (float*)p;
    cudaGetSymbolAddress(&p, g_dw);  float* dwp  = (float*)p;
    cudaGetSymbolAddress(&p, g_W2);  float* w2p  = (float*)p;
    cudaGetSymbolAddress(&p, g_Wh);  __nv_bfloat16* whp = (__nv_bfloat16*)p;
    cudaGetSymbolAddress(&p, g_Wl);  __nv_bfloat16* wlp = (__nv_bfloat16*)p;
    cudaGetSymbolAddress(&p, g_Bh);  __nv_bfloat16* bhp = (__nv_bfloat16*)p;
    cudaGetSymbolAddress(&p, g_Bl);  __nv_bfloat16* blp = (__nv_bfloat16*)p;
    cudaGetSymbolAddress(&p, g_W2h); __nv_bfloat16* w2hp = (__nv_bfloat16*)p;
    cudaGetSymbolAddress(&p, g_W2l); __nv_bfloat16* w2lp = (__nv_bfloat16*)p;

    cudaFuncSetAttribute(mma_gemm, cudaFuncAttributeMaxDynamicSharedMemorySize, 2 * STAGE_BYTES);

    // 0) zero norm accumulators
    zero_normsq<<<(BQ * 2 * CDIM + 255) / 256, 256>>>();

    // 1) split qkv_w -> bf16 hi/lo
    split_elems<<<(TC * CDIM + 255) / 256, 256>>>(qkv_w, whp, wlp, TC * CDIM);

    // 2) transpose+split x: [b][384][HW] -> [b][HW][384] bf16 hi/lo
    transpose_split<<<dim3(HW / 32, CDIM / 32, BQ), dim3(32, 8)>>>(
        x, bhp, blp, (long long)CDIM * HW, (long long)HW * CDIM);

    // 3) qkv = qkv_w @ x via HMMA (3-split bf16): M=1152
    mma_gemm<<<dim3(HW / 128, TC / 128, BQ), 256, 2 * STAGE_BYTES>>>(
        whp, wlp, bhp, blp, qkvp,
        0LL, (long long)HW * CDIM, (long long)TC * HW);

    // 4) tiled depthwise 3x3 + fused q/k norm accumulation
    dwconv_kernel<<<dim3(HP / 16, TC, BQ), 256>>>(dw_w);

    // 5) gram partials
    gram_kernel<<<dim3(NSPLIT, NHEAD, BQ), 256>>>();

    // 6) reduce + scale
    attn_finalize_kernel<<<BQ * NHEAD, 256>>>(temp);

    // 7) top-k softmax combine
    topk_kernel<<<BQ * NHEAD, 64>>>(a1, a2, a3, a4);

    // 8) W2 = proj @ blockdiag(P), then split to bf16 hi/lo
    w2_kernel<<<dim3(NHEAD, BQ), 384>>>(proj_w);
    split_elems<<<(BQ * CDIM * CDIM + 255) / 256, 256>>>(w2p, w2hp, w2lp, BQ * CDIM * CDIM);

    // 9) transpose+split v (g_dw channels 768..1151) -> [b][HW][384] bf16 hi/lo
    transpose_split<<<dim3(HW / 32, CDIM / 32, BQ), dim3(32, 8)>>>(
        dwp + (long long)2 * CDIM * HW, bhp, blp, (long long)TC * HW, (long long)HW * CDIM);

    // 10) y = W2 @ v via HMMA: M=384
    mma_gemm<<<dim3(HW / 128, CDIM / 128, BQ), 256, 2 * STAGE_BYTES>>>(
        w2hp, w2lp, bhp, blp, y,
        (long long)CDIM * CDIM, (long long)HW * CDIM, (long long)CDIM * HW);
}

// round 12
// speedup vs baseline: 1.6050x; 1.6050x over previous
#include <cuda_runtime.h>
#include <cuda_bf16.h>
#include <cstdint>
#include <math.h>

// Problem constants
#define BQ      4
#define CDIM    384
#define TC      1152          // 3*CDIM
#define HP      128
#define WP      128
#define HW      16384         // HP*WP
#define NHEAD   8
#define CH      48            // per-head channels
#define NSPLIT  32            // split-K for gram

// ---------------- scratch (device globals; no runtime allocation) -------------
__device__ float g_qkv[(long long)BQ * TC * HW];     // qkv after 1x1 conv
__device__ float g_dw [(long long)BQ * TC * HW];     // after depthwise 3x3
__device__ float g_normsq[BQ * 2 * CDIM];            // q,k channel squared L2 norms
__device__ float g_partial[(long long)BQ * NHEAD * CH * CH * NSPLIT];
__device__ float g_attn[BQ * NHEAD * CH * CH];
__device__ float g_P   [BQ * NHEAD * CH * CH];       // combined softmax mix
__device__ float g_W2  [BQ * CDIM * CDIM];           // proj @ blockdiag(P)

// bf16 split operands
__device__ __align__(16) __nv_bfloat16 g_Wh[TC * CDIM];
__device__ __align__(16) __nv_bfloat16 g_Wl[TC * CDIM];
__device__ __align__(16) __nv_bfloat16 g_Bh[(long long)BQ * HW * CDIM];  // X^T then V^T
__device__ __align__(16) __nv_bfloat16 g_Bl[(long long)BQ * HW * CDIM];
__device__ __align__(16) __nv_bfloat16 g_W2h[BQ * CDIM * CDIM];
__device__ __align__(16) __nv_bfloat16 g_W2l[BQ * CDIM * CDIM];

// ======================= HMMA (mma.sync) helpers ==============================
__device__ __forceinline__ uint32_t smem_u32(const void* p) {
    uint32_t a;
    asm("{ .reg .u64 t; cvta.to.shared.u64 t, %1; cvt.u32.u64 %0, t; }" : "=r"(a) : "l"(p));
    return a;
}
__device__ __forceinline__ void cp16(uint32_t s, const void* g) {
    asm volatile("cp.async.cg.shared.global [%0], [%1], 16;" :: "r"(s), "l"(g));
}
#define CP_COMMIT() asm volatile("cp.async.commit_group;" ::: "memory")
#define CP_WAIT(n)  asm volatile("cp.async.wait_group %0;" :: "n"(n) : "memory")

__device__ __forceinline__ void ldm4(uint32_t* r, uint32_t addr) {
    asm volatile("ldmatrix.sync.aligned.m8n8.x4.shared.b16 {%0,%1,%2,%3}, [%4];"
        : "=r"(r[0]), "=r"(r[1]), "=r"(r[2]), "=r"(r[3]) : "r"(addr));
}
__device__ __forceinline__ void mma16816(float* d, const uint32_t* a, uint32_t b0, uint32_t b1) {
    asm volatile("mma.sync.aligned.m16n8k16.row.col.f32.bf16.bf16.f32 "
        "{%0,%1,%2,%3}, {%4,%5,%6,%7}, {%8,%9}, {%0,%1,%2,%3};"
        : "+f"(d[0]), "+f"(d[1]), "+f"(d[2]), "+f"(d[3])
        : "r"(a[0]), "r"(a[1]), "r"(a[2]), "r"(a[3]), "r"(b0), "r"(b1));
}

#define SMEM_SWZ(x) ((x) ^ (((x) >> 3) & 0x70))
#define TILE_BYTES  16384     // one 128x64 bf16 tile
#define STAGE_BYTES 65536     // Ah + Al + Bh + Bl tiles
#define NKC 6                 // 6 K-chunks of 64 (K=384)

// ======================= HMMA GEMM kernel =====================================
// C[M,16384] = A[M,384] * Bt[16384,384]^T, 3-way bf16 split (Ah*Bh + Ah*Bl + Al*Bh)
// All 4 operand tiles loaded once per K-chunk; 3 term-passes per chunk.
__global__ __launch_bounds__(256) void mma_gemm(
    const __nv_bfloat16* __restrict__ Ah, const __nv_bfloat16* __restrict__ Al,
    const __nv_bfloat16* __restrict__ Bh, const __nv_bfloat16* __restrict__ Bl,
    float* __restrict__ C, long long aB, long long bB, long long cB)
{
    extern __shared__ char smem[];
    const uint32_t sb = smem_u32(smem);
    const int tid = threadIdx.x, wid = tid >> 5, lid = tid & 31;
    const int b = blockIdx.z;
    Ah += b * aB; Al += b * aB; Bh += b * bB; Bl += b * bB; C += b * cB;
    const long long m0 = (long long)blockIdx.y * 128;
    const long long n0 = (long long)blockIdx.x * 128;

    const int warp_m = wid & 1, warp_n = wid >> 1;   // 2 x 4 warp grid
    const int rbaseA = warp_m * 64;                  // 64 M-rows per warp
    const int nbaseB = warp_n * 32;                  // 32 N-cols per warp
    const int lr = lid & 15, lh = lid >> 4;

    float acc[4][4][4];
#pragma unroll
    for (int mi = 0; mi < 4; mi++)
#pragma unroll
        for (int ni = 0; ni < 4; ni++)
#pragma unroll
            for (int q = 0; q < 4; q++) acc[mi][ni][q] = 0.f;

    // load all 4 tiles (Ah, Al, Bh, Bl) for K-chunk kc into stage st
    auto load_chunk = [&](int kc, int st) {
        const int ko = kc * 64;
        const __nv_bfloat16* gp[4] = { Ah + m0 * CDIM + ko, Al + m0 * CDIM + ko,
                                       Bh + n0 * CDIM + ko, Bl + n0 * CDIM + ko };
        const uint32_t ds = sb + st * STAGE_BYTES;
#pragma unroll
        for (int i = 0; i < 4; i++) {
            const int lin = tid + i * 256;           // 0..1023
            const int row = lin >> 3, seg = lin & 7;
            const uint32_t sw = SMEM_SWZ(row * 128 + seg * 16);
            const long long go = (long long)row * CDIM + seg * 8;
#pragma unroll
            for (int t = 0; t < 4; t++)
                cp16(ds + t * TILE_BYTES + sw, gp[t] + go);
        }
    };

    load_chunk(0, 0); CP_COMMIT();

    for (int c = 0; c < NKC; c++) {
        __syncthreads();                         // previous compute done everywhere
        if (c + 1 < NKC) { load_chunk(c + 1, (c + 1) & 1); CP_COMMIT(); CP_WAIT(1); }
        else             { CP_WAIT(0); }
        __syncthreads();                         // stage (c&1) visible to all warps

        const uint32_t dAh = sb + (c & 1) * STAGE_BYTES;
        const uint32_t dAl = dAh + TILE_BYTES;
        const uint32_t dBh = dAh + 2 * TILE_BYTES;
        const uint32_t dBl = dAh + 3 * TILE_BYTES;
#pragma unroll
        for (int ks = 0; ks < 4; ks++) {
            const int cb = ks * 32 + lh * 16;    // k-step byte offset (+8-col half per lane)
            uint32_t ah[4][4], al[4][4], bh[2][4], bl[2][4];
#pragma unroll
            for (int mi = 0; mi < 4; mi++) {
                const uint32_t ro = SMEM_SWZ((rbaseA + mi * 16 + lr) * 128 + cb);
                ldm4(ah[mi], dAh + ro);
                ldm4(al[mi], dAl + ro);
            }
#pragma unroll
            for (int nh = 0; nh < 2; nh++) {
                const uint32_t ro = SMEM_SWZ((nbaseB + nh * 16 + lr) * 128 + cb);
                ldm4(bh[nh], dBh + ro);
                ldm4(bl[nh], dBl + ro);
            }
            // term 1: Ah * Bh
#pragma unroll
            for (int mi = 0; mi < 4; mi++)
#pragma unroll
                for (int ni = 0; ni < 4; ni++)
                    mma16816(acc[mi][ni], ah[mi],
                             bh[ni >> 1][ni & 1], bh[ni >> 1][2 + (ni & 1)]);
            // term 2: Ah * Bl
#pragma unroll
            for (int mi = 0; mi < 4; mi++)
#pragma unroll
                for (int ni = 0; ni < 4; ni++)
                    mma16816(acc[mi][ni], ah[mi],
                             bl[ni >> 1][ni & 1], bl[ni >> 1][2 + (ni & 1)]);
            // term 3: Al * Bh
#pragma unroll
            for (int mi = 0; mi < 4; mi++)
#pragma unroll
                for (int ni = 0; ni < 4; ni++)
                    mma16816(acc[mi][ni], al[mi],
                             bh[ni >> 1][ni & 1], bh[ni >> 1][2 + (ni & 1)]);
        }
    }

    // epilogue: direct stores (fragment mapping: c0,c1 @ (g,2t), c2,c3 @ (g+8,2t))
    const int g = lid >> 2, t2 = (lid & 3) * 2;
#pragma unroll
    for (int mi = 0; mi < 4; mi++)
#pragma unroll
        for (int ni = 0; ni < 4; ni++) {
            const long long row = m0 + rbaseA + mi * 16 + g;
            const long long col = n0 + nbaseB + ni * 8 + t2;
            float* cp = C + row * HW + col;
            *(float2*)cp              = make_float2(acc[mi][ni][0], acc[mi][ni][1]);
            *(float2*)(cp + 8LL * HW) = make_float2(acc[mi][ni][2], acc[mi][ni][3]);
        }
}

// ---------------- fp32 -> bf16 hi/lo elementwise ------------------------------
__global__ __launch_bounds__(256) void split_elems(
    const float* __restrict__ src, __nv_bfloat16* __restrict__ dh,
    __nv_bfloat16* __restrict__ dl, int n)
{
    int i = blockIdx.x * 256 + threadIdx.x;
    if (i < n) {
        float v = src[i];
        __nv_bfloat16 h = __float2bfloat16(v);
        dh[i] = h;
        dl[i] = __float2bfloat16(v - __bfloat162float(h));
    }
}

// ---------------- transpose [C][N] -> [N][C] + bf16 hi/lo split ---------------
__global__ __launch_bounds__(256) void transpose_split(
    const float* __restrict__ src, __nv_bfloat16* __restrict__ dh,
    __nv_bfloat16* __restrict__ dl, long long sBatch, long long dBatch)
{
    __shared__ float t[32][33];
    const int b = blockIdx.z;
    src += b * sBatch; dh += b * dBatch; dl += b * dBatch;
    const int n0 = blockIdx.x * 32, c0 = blockIdx.y * 32;
    const int tx = threadIdx.x, ty = threadIdx.y;   // 32 x 8
#pragma unroll
    for (int i = 0; i < 4; i++)
        t[ty + 8 * i][tx] = src[(long long)(c0 + ty + 8 * i) * HW + n0 + tx];
    __syncthreads();
#pragma unroll
    for (int i = 0; i < 4; i++) {
        float v = t[tx][ty + 8 * i];
        __nv_bfloat16 h = __float2bfloat16(v);
        long long o = (long long)(n0 + ty + 8 * i) * CDIM + c0 + tx;
        dh[o] = h;
        dl[o] = __float2bfloat16(v - __bfloat162float(h));
    }
}

// ---------------- zero the squared-norm accumulators --------------------------
__global__ void zero_normsq()
{
    int i = blockIdx.x * 256 + threadIdx.x;
    if (i < BQ * 2 * CDIM) g_normsq[i] = 0.f;
}

// ---------------- tiled depthwise 3x3 + fused q/k norm accumulation -----------
// block: 256 threads computes one 16x128 output strip of one (b, ch)
__global__ __launch_bounds__(256) void dwconv_kernel(const float* __restrict__ dw_w)
{
    const int strip = blockIdx.x;          // 0..7
    const int ch    = blockIdx.y;          // 0..1151
    const int b     = blockIdx.z;
    const int y0    = strip * 16;
    const float* in = g_qkv + ((long long)b * TC + ch) * HW;
    float* out      = g_dw  + ((long long)b * TC + ch) * HW;

    __shared__ float tile[18][132];
    const int tid = threadIdx.x;

    float w[9];
#pragma unroll
    for (int i = 0; i < 9; i++) w[i] = __ldg(dw_w + ch * 9 + i);

    // load 18 x 130 halo tile (x in [-1,128], y in [y0-1, y0+16])
    for (int i = tid; i < 18 * 130; i += 256) {
        const int r = i / 130, c = i % 130;
        const int yy = y0 + r - 1, xx = c - 1;
        float v = 0.f;
        if (yy >= 0 && yy < HP && xx >= 0 && xx < WP) v = in[yy * WP + xx];
        tile[r][c] = v;
    }
    __syncthreads();

    float ss = 0.f;
#pragma unroll
    for (int i = 0; i < 8; i++) {
        const int o = tid + i * 256;           // 0..2047
        const int r = o >> 7, c = o & 127;     // r 0..15, c 0..127
        float s = w[0] * tile[r][c]     + w[1] * tile[r][c + 1]     + w[2] * tile[r][c + 2]
                + w[3] * tile[r + 1][c] + w[4] * tile[r + 1][c + 1] + w[5] * tile[r + 1][c + 2]
                + w[6] * tile[r + 2][c] + w[7] * tile[r + 2][c + 1] + w[8] * tile[r + 2][c + 2];
        out[(y0 + r) * WP + c] = s;
        ss += s * s;
    }

    // fused squared-norm accumulation for q/k channels
    if (ch < 2 * CDIM) {
        __shared__ float red[8];
#pragma unroll
        for (int o = 16; o > 0; o >>= 1) ss += __shfl_xor_sync(0xFFFFFFFFu, ss, o);
        const int wd = tid >> 5, lane = tid & 31;
        if (lane == 0) red[wd] = ss;
        __syncthreads();
        if (wd == 0) {
            ss = (lane < 8) ? red[lane] : 0.f;
#pragma unroll
            for (int o = 4; o > 0; o >>= 1) ss += __shfl_xor_sync(0xFFFFFFFFu, ss, o);
            if (lane == 0) atomicAdd(&g_normsq[b * 2 * CDIM + ch], ss);
        }
    }
}

// ---------------- gram partials (split-K) -------------------------------------
__global__ __launch_bounds__(256) void gram_kernel()
{
    const int s = blockIdx.x;
    const int h = blockIdx.y;
    const int b = blockIdx.z;

    const float* qbase = g_dw + ((long long)b * TC + h * CH) * HW;
    const float* kbase = g_dw + ((long long)b * TC + CDIM + h * CH) * HW;

    __shared__ float qs[64][49];
    __shared__ float ks[64][49];

    const int tid = threadIdx.x;
    const int ty = tid >> 4, tx = tid & 15;
    const int i0 = ty * 3, j0 = tx * 3;

    float acc[3][3] = {{0.f,0.f,0.f},{0.f,0.f,0.f},{0.f,0.f,0.f}};

    const int nbase0 = s * (HW / NSPLIT);
    for (int nb = 0; nb < HW / NSPLIT; nb += 64) {
        const int nbase = nbase0 + nb;
#pragma unroll
        for (int t = 0; t < 3; t++) {
            int lin = tid + t * 256;
            int row = lin >> 4;
            int c4  = (lin & 15) * 4;
            float4 v = *(const float4*)(qbase + (long long)row * HW + nbase + c4);
            qs[c4 + 0][row] = v.x; qs[c4 + 1][row] = v.y;
            qs[c4 + 2][row] = v.z; qs[c4 + 3][row] = v.w;
            float4 u = *(const float4*)(kbase + (long long)row * HW + nbase + c4);
            ks[c4 + 0][row] = u.x; ks[c4 + 1][row] = u.y;
            ks[c4 + 2][row] = u.z; ks[c4 + 3][row] = u.w;
        }
        __syncthreads();
#pragma unroll 8
        for (int n = 0; n < 64; n++) {
            float q0 = qs[n][i0], q1 = qs[n][i0 + 1], q2 = qs[n][i0 + 2];
            float k0 = ks[n][j0], k1 = ks[n][j0 + 1], k2 = ks[n][j0 + 2];
            acc[0][0] += q0 * k0; acc[0][1] += q0 * k1; acc[0][2] += q0 * k2;
            acc[1][0] += q1 * k0; acc[1][1] += q1 * k1; acc[1][2] += q1 * k2;
            acc[2][0] += q2 * k0; acc[2][1] += q2 * k1; acc[2][2] += q2 * k2;
        }
        __syncthreads();
    }

    const int bh = b * NHEAD + h;
#pragma unroll
    for (int i = 0; i < 3; i++)
#pragma unroll
        for (int j = 0; j < 3; j++)
            g_partial[((long long)bh * CH * CH + (i0 + i) * CH + (j0 + j)) * NSPLIT + s] = acc[i][j];
}

// ---------------- reduce splits + scale by temperature / rsqrt(normsq) --------
__global__ __launch_bounds__(256) void attn_finalize_kernel(const float* __restrict__ temperature)
{
    const int bh = blockIdx.x;
    const int b = bh / NHEAD, h = bh % NHEAD;
    const float temp = temperature[h];
    for (int idx = threadIdx.x; idx < CH * CH; idx += 256) {
        int i = idx / CH, j = idx % CH;
        float sum = 0.f;
        const float* p = g_partial + ((long long)bh * CH * CH + idx) * NSPLIT;
#pragma unroll
        for (int s = 0; s < NSPLIT; s++) sum += p[s];
        float nq2 = g_normsq[b * 2 * CDIM + h * CH + i];
        float nk2 = g_normsq[b * 2 * CDIM + CDIM + h * CH + j];
        g_attn[bh * CH * CH + idx] = sum * temp * rsqrtf(nq2 * nk2);
    }
}

// ---------------- top-k softmax combine ---------------------------------------
__global__ void topk_kernel(const float* __restrict__ a1, const float* __restrict__ a2,
                            const float* __restrict__ a3, const float* __restrict__ a4)
{
    const int bh = blockIdx.x;
    const int i = threadIdx.x;
    if (i >= CH) return;

    const float* row = g_attn + bh * CH * CH + i * CH;
    float v[CH], srt[CH];
#pragma unroll
    for (int j = 0; j < CH; j++) { v[j] = row[j]; srt[j] = v[j]; }

    for (int a = 1; a < CH; a++) {
        float key = srt[a];
        int bb = a - 1;
        while (bb >= 0 && srt[bb] < key) { srt[bb + 1] = srt[bb]; bb--; }
        srt[bb + 1] = key;
    }

    const float m = srt[0];
    float e[CH];
#pragma unroll
    for (int j = 0; j < CH; j++) e[j] = expf(v[j] - m);

    const int kidx[4] = {23, 31, 35, 37};
    const float aw[4] = {a1[0], a2[0], a3[0], a4[0]};

    float P[CH];
#pragma unroll
    for (int j = 0; j < CH; j++) P[j] = 0.f;

    for (int l = 0; l < 4; l++) {
        float thr = srt[kidx[l]];
        float denom = 0.f;
        for (int j = 0; j < CH; j++) if (v[j] >= thr) denom += e[j];
        float sc = aw[l] / denom;
        for (int j = 0; j < CH; j++) if (v[j] >= thr) P[j] += sc * e[j];
    }

    float* out = g_P + bh * CH * CH + i * CH;
#pragma unroll
    for (int j = 0; j < CH; j++) out[j] = P[j];
}

// ---------------- W2[b] = proj @ blockdiag(P[b,h]) ----------------------------
__global__ __launch_bounds__(384) void w2_kernel(const float* __restrict__ proj)
{
    const int h = blockIdx.x, b = blockIdx.y;
    const int bh = b * NHEAD + h;
    const int o = threadIdx.x;

    __shared__ float Ps[CH][CH];
    for (int idx = o; idx < CH * CH; idx += 384)
        Ps[idx / CH][idx % CH] = g_P[bh * CH * CH + idx];
    __syncthreads();

    float pr[CH];
#pragma unroll
    for (int cl = 0; cl < CH; cl++) pr[cl] = proj[o * CDIM + h * CH + cl];

    float* wout = g_W2 + ((long long)b * CDIM + o) * CDIM + h * CH;
    for (int d = 0; d < CH; d++) {
        float s = 0.f;
#pragma unroll
        for (int cl = 0; cl < CH; cl++) s += pr[cl] * Ps[cl][d];
        wout[d] = s;
    }
}

// ---------------- launch ------------------------------------------------------
extern "C" void kernel_launch(void* const* d_in, const int* in_sizes, int n_in,
                              void* d_out, int out_size)
{
    const float* x      = (const float*)d_in[0];
    const float* qkv_w  = (const float*)d_in[1];
    const float* dw_w   = (const float*)d_in[2];
    const float* proj_w = (const float*)d_in[3];
    const float* temp   = (const float*)d_in[4];
    const float* a1     = (const float*)d_in[5];
    const float* a2     = (const float*)d_in[6];
    const float* a3     = (const float*)d_in[7];
    const float* a4     = (const float*)d_in[8];
    float* y            = (float*)d_out;

    void* p;
    cudaGetSymbolAddress(&p, g_qkv); float* qkvp = (float*)p;
    cudaGetSymbolAddress(&p, g_dw);  float* dwp  = (float*)p;
    cudaGetSymbolAddress(&p, g_W2);  float* w2p  = (float*)p;
    cudaGetSymbolAddress(&p, g_Wh);  __nv_bfloat16* whp = (__nv_bfloat16*)p;
    cudaGetSymbolAddress(&p, g_Wl);  __nv_bfloat16* wlp = (__nv_bfloat16*)p;
    cudaGetSymbolAddress(&p, g_Bh);  __nv_bfloat16* bhp = (__nv_bfloat16*)p;
    cudaGetSymbolAddress(&p, g_Bl);  __nv_bfloat16* blp = (__nv_bfloat16*)p;
    cudaGetSymbolAddress(&p, g_W2h); __nv_bfloat16* w2hp = (__nv_bfloat16*)p;
    cudaGetSymbolAddress(&p, g_W2l); __nv_bfloat16* w2lp = (__nv_bfloat16*)p;

    cudaFuncSetAttribute(mma_gemm, cudaFuncAttributeMaxDynamicSharedMemorySize, 2 * STAGE_BYTES);

    // 0) zero norm accumulators
    zero_normsq<<<(BQ * 2 * CDIM + 255) / 256, 256>>>();

    // 1) split qkv_w -> bf16 hi/lo
    split_elems<<<(TC * CDIM + 255) / 256, 256>>>(qkv_w, whp, wlp, TC * CDIM);

    // 2) transpose+split x: [b][384][HW] -> [b][HW][384] bf16 hi/lo
    transpose_split<<<dim3(HW / 32, CDIM / 32, BQ), dim3(32, 8)>>>(
        x, bhp, blp, (long long)CDIM * HW, (long long)HW * CDIM);

    // 3) qkv = qkv_w @ x via HMMA (3-split bf16, fused chunk load): M=1152
    mma_gemm<<<dim3(HW / 128, TC / 128, BQ), 256, 2 * STAGE_BYTES>>>(
        whp, wlp, bhp, blp, qkvp,
        0LL, (long long)HW * CDIM, (long long)TC * HW);

    // 4) tiled depthwise 3x3 + fused q/k norm accumulation
    dwconv_kernel<<<dim3(HP / 16, TC, BQ), 256>>>(dw_w);

    // 5) gram partials
    gram_kernel<<<dim3(NSPLIT, NHEAD, BQ), 256>>>();

    // 6) reduce + scale
    attn_finalize_kernel<<<BQ * NHEAD, 256>>>(temp);

    // 7) top-k softmax combine
    topk_kernel<<<BQ * NHEAD, 64>>>(a1, a2, a3, a4);

    // 8) W2 = proj @ blockdiag(P), then split to bf16 hi/lo
    w2_kernel<<<dim3(NHEAD, BQ), 384>>>(proj_w);
    split_elems<<<(BQ * CDIM * CDIM + 255) / 256, 256>>>(w2p, w2hp, w2lp, BQ * CDIM * CDIM);

    // 9) transpose+split v (g_dw channels 768..1151) -> [b][HW][384] bf16 hi/lo
    transpose_split<<<dim3(HW / 32, CDIM / 32, BQ), dim3(32, 8)>>>(
        dwp + (long long)2 * CDIM * HW, bhp, blp, (long long)TC * HW, (long long)HW * CDIM);

    // 10) y = W2 @ v via HMMA: M=384
    mma_gemm<<<dim3(HW / 128, CDIM / 128, BQ), 256, 2 * STAGE_BYTES>>>(
        w2hp, w2lp, bhp, blp, y,
        (long long)CDIM * CDIM, (long long)HW * CDIM, (long long)CDIM * HW);
}